// round 3
// baseline (speedup 1.0000x reference)
#include <cuda_runtime.h>

// ---------------------------------------------------------------------------
// CrossVariableAttention: fused LN + QKV GEMM + 4x4 cross-head attention +
// proj GEMM + residual.  fp32 throughout, fma.rn.f32x2 packed math.
//
// Shapes: B=4, L=8, C=256, S=64, W=64  -> N = 131072 rows, 256 channels.
// Input/output layout (B,L,C,S,W): element [row n, chan c] at
//   outer*C*4096 + c*4096 + inner,  outer = n>>12, inner = n&4095.
// ---------------------------------------------------------------------------

#define TM 32          // rows per CTA
#define CDIM 256
#define NQ 768
#define KS 8           // K-slice depth for weight staging

// shared memory layout (float offsets)
#define X_S        0           // raw x        [32][261]
#define X_STRIDE   261
#define XN_T       8352        // xnorm^T / y^T [256][34]  (row-pairs packed for f32x2)
#define XN_STRIDE  34
#define QKV        17056       // qkv / out    [32][773]
#define QKV_STRIDE 773
#define BS         41792       // weight slice [8][772]
#define BS_STRIDE  772
#define SMEM_FLOATS (41792 + KS * BS_STRIDE)   // 47968 floats = 191872 bytes

__device__ __forceinline__ unsigned long long pack2(float v) {
    unsigned long long r;
    asm("mov.b64 %0, {%1, %1};" : "=l"(r) : "r"(__float_as_uint(v)));
    return r;
}
__device__ __forceinline__ void fma2(unsigned long long& d, unsigned long long a,
                                     unsigned long long b) {
    asm("fma.rn.f32x2 %0, %1, %2, %0;" : "+l"(d) : "l"(a), "l"(b));
}
__device__ __forceinline__ void unpack2(unsigned long long v, float& lo, float& hi) {
    unsigned int l, h;
    asm("mov.b64 {%0, %1}, %2;" : "=r"(l), "=r"(h) : "l"(v));
    lo = __uint_as_float(l);
    hi = __uint_as_float(h);
}

__global__ __launch_bounds__(256, 1)
void cva_kernel(const float* __restrict__ x, const float* __restrict__ wqkv,
                const float* __restrict__ wproj, const float* __restrict__ bproj,
                const float* __restrict__ gamma, const float* __restrict__ beta,
                float* __restrict__ out)
{
    extern __shared__ float sm[];
    const int t = threadIdx.x;
    const long long n0 = (long long)blockIdx.x * TM;
    const long long outer = n0 >> 12;
    const int inner = (int)(n0 & 4095);
    const float* xg = x + outer * (CDIM * 4096LL) + inner;
    float* og = out + outer * (CDIM * 4096LL) + inner;

    // ---- Phase A: load x tile (coalesced: 32 rows contiguous per channel) ----
    #pragma unroll
    for (int i = 0; i < 32; i++) {
        int idx = i * 256 + t;
        int c = idx >> 5, r = idx & 31;
        sm[X_S + r * X_STRIDE + c] = xg[(long long)c * 4096 + r];
    }
    __syncthreads();

    // ---- Phase B: LayerNorm (warp handles 4 rows, 8 lanes per row) ----
    {
        int r = (t >> 5) * 4 + ((t & 31) >> 3);
        int sub = t & 7;
        const float* xr = &sm[X_S + r * X_STRIDE];
        float s = 0.f, s2 = 0.f;
        #pragma unroll
        for (int i = 0; i < 32; i++) {
            float v = xr[sub + 8 * i];
            s += v; s2 += v * v;
        }
        #pragma unroll
        for (int m = 1; m < 8; m <<= 1) {
            s  += __shfl_xor_sync(0xffffffffu, s,  m);
            s2 += __shfl_xor_sync(0xffffffffu, s2, m);
        }
        float mean = s * (1.f / 256.f);
        float var  = fmaf(-mean, mean, s2 * (1.f / 256.f));
        float rstd = rsqrtf(var + 1e-5f);
        #pragma unroll
        for (int i = 0; i < 32; i++) {
            int k = sub + 8 * i;
            float v = (xr[k] - mean) * rstd * __ldg(&gamma[k]) + __ldg(&beta[k]);
            sm[XN_T + k * XN_STRIDE + r] = v;   // transposed, row-pairs contiguous
        }
    }
    // (LN->GEMM1 visibility covered by the first __syncthreads inside the loop)

    // ---- Phase C: GEMM1  qkv[r][j] = sum_k xn[r][k] * wqkv[j][k] ----
    // thread owns columns {t, t+256, t+512}; 16 row-pairs each (f32x2 acc)
    unsigned long long acc0[16], acc1[16], acc2[16];
    #pragma unroll
    for (int i = 0; i < 16; i++) { acc0[i] = 0ull; acc1[i] = 0ull; acc2[i] = 0ull; }

    float4 pw[6];
    #pragma unroll
    for (int i = 0; i < 6; i++) {           // prefetch slice 0
        int e = t * 4 + i * 1024;           // 768*8 floats per slice
        int j = e >> 3, kk = e & 7;
        pw[i] = *(const float4*)&wqkv[j * 256 + kk];
    }
    #pragma unroll 1
    for (int s = 0; s < 32; s++) {
        __syncthreads();                    // safe to overwrite Bs
        #pragma unroll
        for (int i = 0; i < 6; i++) {
            int e = t * 4 + i * 1024;
            int j = e >> 3, kk = e & 7;
            sm[BS + (kk + 0) * BS_STRIDE + j] = pw[i].x;
            sm[BS + (kk + 1) * BS_STRIDE + j] = pw[i].y;
            sm[BS + (kk + 2) * BS_STRIDE + j] = pw[i].z;
            sm[BS + (kk + 3) * BS_STRIDE + j] = pw[i].w;
        }
        __syncthreads();                    // Bs ready
        if (s + 1 < 32) {                   // prefetch next slice (latency hidden)
            int k0n = (s + 1) * KS;
            #pragma unroll
            for (int i = 0; i < 6; i++) {
                int e = t * 4 + i * 1024;
                int j = e >> 3, kk = e & 7;
                pw[i] = *(const float4*)&wqkv[j * 256 + k0n + kk];
            }
        }
        int k0 = s * KS;
        #pragma unroll
        for (int kk = 0; kk < KS; kk++) {
            float b0 = sm[BS + kk * BS_STRIDE + t];
            float b1 = sm[BS + kk * BS_STRIDE + 256 + t];
            float b2 = sm[BS + kk * BS_STRIDE + 512 + t];
            unsigned long long B0 = pack2(b0), B1 = pack2(b1), B2 = pack2(b2);
            const unsigned long long* ar =
                (const unsigned long long*)&sm[XN_T + (k0 + kk) * XN_STRIDE];
            #pragma unroll
            for (int r2 = 0; r2 < 16; r2++) {
                unsigned long long a = ar[r2];   // broadcast LDS.64, conflict-free
                fma2(acc0[r2], a, B0);
                fma2(acc1[r2], a, B1);
                fma2(acc2[r2], a, B2);
            }
        }
    }
    #pragma unroll
    for (int r2 = 0; r2 < 16; r2++) {       // write qkv tile
        float lo, hi;
        unpack2(acc0[r2], lo, hi);
        sm[QKV + (2 * r2) * QKV_STRIDE + t] = lo;
        sm[QKV + (2 * r2 + 1) * QKV_STRIDE + t] = hi;
        unpack2(acc1[r2], lo, hi);
        sm[QKV + (2 * r2) * QKV_STRIDE + 256 + t] = lo;
        sm[QKV + (2 * r2 + 1) * QKV_STRIDE + 256 + t] = hi;
        unpack2(acc2[r2], lo, hi);
        sm[QKV + (2 * r2) * QKV_STRIDE + 512 + t] = lo;
        sm[QKV + (2 * r2 + 1) * QKV_STRIDE + 512 + t] = hi;
    }
    __syncthreads();

    // ---- Phase D: per-row 4x4 cross-head attention ----
    // q[h][d] = qkv[12d+3h], k = +1, v = +2;  y[c=4d+h] = sum_g attn[h][g] v[g][d]
    {
        int r = (t >> 5) * 4 + ((t & 31) >> 3);
        int sub = t & 7;                    // 8 lanes per row, d-slice of 8 each
        const float* qk = &sm[QKV + r * QKV_STRIDE];
        float lg[16];
        #pragma unroll
        for (int i = 0; i < 16; i++) lg[i] = 0.f;
        #pragma unroll
        for (int i = 0; i < 8; i++) {
            const float* p = qk + 12 * (sub * 8 + i);
            float q0 = p[0], k0v = p[1];
            float q1 = p[3], k1v = p[4];
            float q2 = p[6], k2v = p[7];
            float q3 = p[9], k3v = p[10];
            lg[0]  = fmaf(q0, k0v, lg[0]);  lg[1]  = fmaf(q0, k1v, lg[1]);
            lg[2]  = fmaf(q0, k2v, lg[2]);  lg[3]  = fmaf(q0, k3v, lg[3]);
            lg[4]  = fmaf(q1, k0v, lg[4]);  lg[5]  = fmaf(q1, k1v, lg[5]);
            lg[6]  = fmaf(q1, k2v, lg[6]);  lg[7]  = fmaf(q1, k3v, lg[7]);
            lg[8]  = fmaf(q2, k0v, lg[8]);  lg[9]  = fmaf(q2, k1v, lg[9]);
            lg[10] = fmaf(q2, k2v, lg[10]); lg[11] = fmaf(q2, k3v, lg[11]);
            lg[12] = fmaf(q3, k0v, lg[12]); lg[13] = fmaf(q3, k1v, lg[13]);
            lg[14] = fmaf(q3, k2v, lg[14]); lg[15] = fmaf(q3, k3v, lg[15]);
        }
        #pragma unroll
        for (int m = 1; m < 8; m <<= 1) {
            #pragma unroll
            for (int i = 0; i < 16; i++)
                lg[i] += __shfl_xor_sync(0xffffffffu, lg[i], m);
        }
        float attn[16];
        #pragma unroll
        for (int h = 0; h < 4; h++) {
            float a0 = lg[h * 4 + 0] * 0.125f, a1 = lg[h * 4 + 1] * 0.125f;
            float a2 = lg[h * 4 + 2] * 0.125f, a3 = lg[h * 4 + 3] * 0.125f;
            float mx = fmaxf(fmaxf(a0, a1), fmaxf(a2, a3));
            float e0 = expf(a0 - mx), e1 = expf(a1 - mx);
            float e2 = expf(a2 - mx), e3 = expf(a3 - mx);
            float inv = 1.f / (e0 + e1 + e2 + e3);
            attn[h * 4 + 0] = e0 * inv; attn[h * 4 + 1] = e1 * inv;
            attn[h * 4 + 2] = e2 * inv; attn[h * 4 + 3] = e3 * inv;
        }
        #pragma unroll
        for (int i = 0; i < 8; i++) {
            int d = sub * 8 + i;
            const float* p = qk + 12 * d;
            float v0 = p[2], v1 = p[5], v2 = p[8], v3 = p[11];
            #pragma unroll
            for (int h = 0; h < 4; h++) {
                float y = attn[h * 4 + 0] * v0 + attn[h * 4 + 1] * v1 +
                          attn[h * 4 + 2] * v2 + attn[h * 4 + 3] * v3;
                sm[XN_T + (4 * d + h) * XN_STRIDE + r] = y;  // y^T reuses xn_t
            }
        }
    }
    __syncthreads();

    // ---- Phase E: GEMM2  out[r][c] = x[r][c] + sum_k y[r][k]*wproj[c][k] + bp[c]
    unsigned long long accP[16];
    #pragma unroll
    for (int i = 0; i < 16; i++) accP[i] = 0ull;

    float4 pv[2];
    #pragma unroll
    for (int i = 0; i < 2; i++) {           // prefetch slice 0 (256*8 floats)
        int e = t * 4 + i * 1024;
        int j = e >> 3, kk = e & 7;
        pv[i] = *(const float4*)&wproj[j * 256 + kk];
    }
    #pragma unroll 1
    for (int s = 0; s < 32; s++) {
        __syncthreads();
        #pragma unroll
        for (int i = 0; i < 2; i++) {
            int e = t * 4 + i * 1024;
            int j = e >> 3, kk = e & 7;
            sm[BS + (kk + 0) * BS_STRIDE + j] = pv[i].x;
            sm[BS + (kk + 1) * BS_STRIDE + j] = pv[i].y;
            sm[BS + (kk + 2) * BS_STRIDE + j] = pv[i].z;
            sm[BS + (kk + 3) * BS_STRIDE + j] = pv[i].w;
        }
        __syncthreads();
        if (s + 1 < 32) {
            int k0n = (s + 1) * KS;
            #pragma unroll
            for (int i = 0; i < 2; i++) {
                int e = t * 4 + i * 1024;
                int j = e >> 3, kk = e & 7;
                pv[i] = *(const float4*)&wproj[j * 256 + k0n + kk];
            }
        }
        int k0 = s * KS;
        #pragma unroll
        for (int kk = 0; kk < KS; kk++) {
            unsigned long long Bv = pack2(sm[BS + kk * BS_STRIDE + t]);
            const unsigned long long* ar =
                (const unsigned long long*)&sm[XN_T + (k0 + kk) * XN_STRIDE];
            #pragma unroll
            for (int r2 = 0; r2 < 16; r2++)
                fma2(accP[r2], ar[r2], Bv);
        }
    }
    {   // epilogue: residual + bias, park in smem (reuse QKV region)
        float bp = __ldg(&bproj[t]);
        #pragma unroll
        for (int r2 = 0; r2 < 16; r2++) {
            float lo, hi;
            unpack2(accP[r2], lo, hi);
            sm[QKV + (2 * r2) * QKV_STRIDE + t] =
                lo + sm[X_S + (2 * r2) * X_STRIDE + t] + bp;
            sm[QKV + (2 * r2 + 1) * QKV_STRIDE + t] =
                hi + sm[X_S + (2 * r2 + 1) * X_STRIDE + t] + bp;
        }
    }
    __syncthreads();

    // ---- Phase F: coalesced store ----
    #pragma unroll
    for (int i = 0; i < 32; i++) {
        int idx = i * 256 + t;
        int c = idx >> 5, r = idx & 31;
        og[(long long)c * 4096 + r] = sm[QKV + r * QKV_STRIDE + c];
    }
}

extern "C" void kernel_launch(void* const* d_in, const int* in_sizes, int n_in,
                              void* d_out, int out_size)
{
    const float* x     = (const float*)d_in[0];
    const float* wqkv  = (const float*)d_in[1];
    const float* wproj = (const float*)d_in[2];
    const float* bproj = (const float*)d_in[3];
    const float* gamma = (const float*)d_in[4];
    const float* beta  = (const float*)d_in[5];
    float* out = (float*)d_out;

    const size_t shmem = SMEM_FLOATS * sizeof(float);   // 191872 B
    cudaFuncSetAttribute(cva_kernel, cudaFuncAttributeMaxDynamicSharedMemorySize,
                         (int)shmem);
    cva_kernel<<<4096, 256, shmem>>>(x, wqkv, wproj, bproj, gamma, beta, out);
}

// round 5
// speedup vs baseline: 1.3709x; 1.3709x over previous
#include <cuda_runtime.h>

// ---------------------------------------------------------------------------
// CrossVariableAttention: fused LN + QKV GEMM + 4x4 cross-head attention +
// proj GEMM + residual.  fp32, fma.rn.f32x2, LDS.128-vectorized register tiles.
//
// B=4, L=8, C=256, S=64, W=64 -> N = 131072 rows, 256 channels.
// element [row n, chan c] at outer*C*4096 + c*4096 + inner.
// ---------------------------------------------------------------------------

#define TM 32

// shared memory layout (float offsets)
#define X_S        0            // raw x          [32][261]
#define X_STRIDE   261
#define XN2        8352         // xnorm^T / y^T  [256][36]  (16B-aligned rows)
#define XN_STRIDE  36
#define QKV        17568        // qkv / out      [32][773]
#define QKV_STRIDE 773
#define BS         42304        // weight slices  2 x [8][768] (linear)
#define SMEM_FLOATS 54592       // 218368 bytes

__device__ float g_wqkv_t[768 * 256];   // [k][j] transposed qkv weight
__device__ float g_wproj_t[256 * 256];  // [k][c] transposed proj weight

__global__ void transpose_w_kernel(const float* __restrict__ wqkv,
                                   const float* __restrict__ wproj) {
    int idx = blockIdx.x * blockDim.x + threadIdx.x;
    if (idx < 768 * 256) {
        int j = idx >> 8, k = idx & 255;
        g_wqkv_t[k * 768 + j] = wqkv[idx];
    }
    if (idx < 256 * 256) {
        int j = idx >> 8, k = idx & 255;
        g_wproj_t[k * 256 + j] = wproj[idx];
    }
}

__device__ __forceinline__ unsigned long long pack2(float v) {
    unsigned long long r;
    asm("mov.b64 %0, {%1, %1};" : "=l"(r) : "r"(__float_as_uint(v)));
    return r;
}
__device__ __forceinline__ void fma2(unsigned long long& d, unsigned long long a,
                                     unsigned long long b) {
    asm("fma.rn.f32x2 %0, %1, %2, %0;" : "+l"(d) : "l"(a), "l"(b));
}
__device__ __forceinline__ void unpack2(unsigned long long v, float& lo, float& hi) {
    unsigned int l, h;
    asm("mov.b64 {%0, %1}, %2;" : "=r"(l), "=r"(h) : "l"(v));
    lo = __uint_as_float(l);
    hi = __uint_as_float(h);
}

__global__ __launch_bounds__(256, 1)
void cva_kernel(const float* __restrict__ x, const float* __restrict__ bproj,
                const float* __restrict__ gamma, const float* __restrict__ beta,
                float* __restrict__ out)
{
    extern __shared__ float sm[];
    const int t = threadIdx.x;
    const int rg = t & 3;        // row group: rows rg*8 .. rg*8+7
    const int cg = t >> 2;       // col group (0..63)
    const long long n0 = (long long)blockIdx.x * TM;
    const long long outer = n0 >> 12;
    const int inner = (int)(n0 & 4095);
    const float* xg = x + outer * (256LL * 4096LL) + inner;
    float* og = out + outer * (256LL * 4096LL) + inner;

    // ---- Phase A: load x tile (coalesced 128B per warp) ----
    #pragma unroll
    for (int i = 0; i < 32; i++) {
        int idx = i * 256 + t;
        int c = idx >> 5, r = idx & 31;
        sm[X_S + r * X_STRIDE + c] = xg[(long long)c * 4096 + r];
    }
    __syncthreads();

    // ---- Phase B: LayerNorm (8 lanes per row) -> xn^T [k][row], stride 36 ----
    {
        int r = (t >> 5) * 4 + ((t & 31) >> 3);
        int sub = t & 7;
        const float* xr = &sm[X_S + r * X_STRIDE];
        float s = 0.f, s2 = 0.f;
        #pragma unroll
        for (int i = 0; i < 32; i++) {
            float v = xr[sub + 8 * i];
            s += v; s2 += v * v;
        }
        #pragma unroll
        for (int m = 1; m < 8; m <<= 1) {
            s  += __shfl_xor_sync(0xffffffffu, s,  m);
            s2 += __shfl_xor_sync(0xffffffffu, s2, m);
        }
        float mean = s * (1.f / 256.f);
        float var  = fmaf(-mean, mean, s2 * (1.f / 256.f));
        float rstd = rsqrtf(var + 1e-5f);
        #pragma unroll
        for (int i = 0; i < 32; i++) {
            int k = sub + 8 * i;
            float v = (xr[k] - mean) * rstd * __ldg(&gamma[k]) + __ldg(&beta[k]);
            sm[XN2 + k * XN_STRIDE + r] = v;
        }
    }

    // ---- Phase C: GEMM1  qkv[r][j] = sum_k xn[r][k]*wqkv_t[k][j] ----
    // thread tile: rows rg*8..+7, cols cg*12..+11 (6 col-pairs f32x2)
    unsigned long long acc[8][6];
    #pragma unroll
    for (int r = 0; r < 8; r++)
        #pragma unroll
        for (int c = 0; c < 6; c++) acc[r][c] = 0ull;

    float4 pw[6];
    #pragma unroll
    for (int i = 0; i < 6; i++) pw[i] = *(const float4*)&g_wqkv_t[t * 4 + i * 1024];
    #pragma unroll
    for (int i = 0; i < 6; i++) ((float4*)&sm[BS])[t + i * 256] = pw[i];
    #pragma unroll
    for (int i = 0; i < 6; i++)
        pw[i] = *(const float4*)&g_wqkv_t[6144 + t * 4 + i * 1024];
    __syncthreads();

    #pragma unroll 1
    for (int s = 0; s < 32; s++) {
        const float* xb = &sm[XN2 + s * (8 * XN_STRIDE) + rg * 8];
        const float* bb = &sm[BS + (s & 1) * 6144 + cg * 12];
        #pragma unroll
        for (int kk = 0; kk < 8; kk++) {
            float4 a0 = *(const float4*)(xb + kk * XN_STRIDE);
            float4 a1 = *(const float4*)(xb + kk * XN_STRIDE + 4);
            unsigned long long A[8];
            A[0] = pack2(a0.x); A[1] = pack2(a0.y);
            A[2] = pack2(a0.z); A[3] = pack2(a0.w);
            A[4] = pack2(a1.x); A[5] = pack2(a1.y);
            A[6] = pack2(a1.z); A[7] = pack2(a1.w);
            ulonglong2 B0 = *(const ulonglong2*)(bb + kk * 768);
            ulonglong2 B1 = *(const ulonglong2*)(bb + kk * 768 + 4);
            ulonglong2 B2 = *(const ulonglong2*)(bb + kk * 768 + 8);
            #pragma unroll
            for (int r = 0; r < 8; r++) {
                fma2(acc[r][0], A[r], B0.x); fma2(acc[r][1], A[r], B0.y);
                fma2(acc[r][2], A[r], B1.x); fma2(acc[r][3], A[r], B1.y);
                fma2(acc[r][4], A[r], B2.x); fma2(acc[r][5], A[r], B2.y);
            }
        }
        if (s + 1 < 32) {
            #pragma unroll
            for (int i = 0; i < 6; i++)
                ((float4*)&sm[BS + ((s + 1) & 1) * 6144])[t + i * 256] = pw[i];
            if (s + 2 < 32) {
                #pragma unroll
                for (int i = 0; i < 6; i++)
                    pw[i] = *(const float4*)&g_wqkv_t[(s + 2) * 6144 + t * 4 + i * 1024];
            }
        }
        __syncthreads();
    }
    // write qkv tile to smem
    #pragma unroll
    for (int r = 0; r < 8; r++) {
        int row = rg * 8 + r;
        float* q = &sm[QKV + row * QKV_STRIDE + cg * 12];
        #pragma unroll
        for (int c = 0; c < 6; c++) {
            float lo, hi;
            unpack2(acc[r][c], lo, hi);
            q[2 * c] = lo; q[2 * c + 1] = hi;
        }
    }
    __syncthreads();

    // ---- Phase D: per-row 4x4 cross-head attention ----
    // q[h][d]=qkv[12d+3h], k=+1, v=+2;  y[4d+h] = sum_g attn[h][g] v[g][d]
    // lane handles d = i*8+sub (bank-conflict-free with stride 773)
    {
        int r = (t >> 5) * 4 + ((t & 31) >> 3);
        int sub = t & 7;
        const float* qk = &sm[QKV + r * QKV_STRIDE];
        float lg[16];
        #pragma unroll
        for (int i = 0; i < 16; i++) lg[i] = 0.f;
        #pragma unroll
        for (int i = 0; i < 8; i++) {
            const float* p = qk + 12 * (i * 8 + sub);
            float q0 = p[0], k0v = p[1];
            float q1 = p[3], k1v = p[4];
            float q2 = p[6], k2v = p[7];
            float q3 = p[9], k3v = p[10];
            lg[0]  = fmaf(q0, k0v, lg[0]);  lg[1]  = fmaf(q0, k1v, lg[1]);
            lg[2]  = fmaf(q0, k2v, lg[2]);  lg[3]  = fmaf(q0, k3v, lg[3]);
            lg[4]  = fmaf(q1, k0v, lg[4]);  lg[5]  = fmaf(q1, k1v, lg[5]);
            lg[6]  = fmaf(q1, k2v, lg[6]);  lg[7]  = fmaf(q1, k3v, lg[7]);
            lg[8]  = fmaf(q2, k0v, lg[8]);  lg[9]  = fmaf(q2, k1v, lg[9]);
            lg[10] = fmaf(q2, k2v, lg[10]); lg[11] = fmaf(q2, k3v, lg[11]);
            lg[12] = fmaf(q3, k0v, lg[12]); lg[13] = fmaf(q3, k1v, lg[13]);
            lg[14] = fmaf(q3, k2v, lg[14]); lg[15] = fmaf(q3, k3v, lg[15]);
        }
        #pragma unroll
        for (int m = 1; m < 8; m <<= 1) {
            #pragma unroll
            for (int i = 0; i < 16; i++)
                lg[i] += __shfl_xor_sync(0xffffffffu, lg[i], m);
        }
        float attn[16];
        #pragma unroll
        for (int h = 0; h < 4; h++) {
            float a0 = lg[h * 4 + 0] * 0.125f, a1 = lg[h * 4 + 1] * 0.125f;
            float a2 = lg[h * 4 + 2] * 0.125f, a3 = lg[h * 4 + 3] * 0.125f;
            float mx = fmaxf(fmaxf(a0, a1), fmaxf(a2, a3));
            float e0 = expf(a0 - mx), e1 = expf(a1 - mx);
            float e2 = expf(a2 - mx), e3 = expf(a3 - mx);
            float inv = 1.f / (e0 + e1 + e2 + e3);
            attn[h * 4 + 0] = e0 * inv; attn[h * 4 + 1] = e1 * inv;
            attn[h * 4 + 2] = e2 * inv; attn[h * 4 + 3] = e3 * inv;
        }
        #pragma unroll
        for (int i = 0; i < 8; i++) {
            int d = i * 8 + sub;
            const float* p = qk + 12 * d;
            float v0 = p[2], v1 = p[5], v2 = p[8], v3 = p[11];
            #pragma unroll
            for (int h = 0; h < 4; h++) {
                float y = attn[h * 4 + 0] * v0 + attn[h * 4 + 1] * v1 +
                          attn[h * 4 + 2] * v2 + attn[h * 4 + 3] * v3;
                sm[XN2 + (4 * d + h) * XN_STRIDE + r] = y;   // y^T, stride 36
            }
        }
    }
    __syncthreads();

    // ---- Phase E: GEMM2  out[r][c] = x + sum_k y[r][k]*wproj_t[k][c] + bp ----
    // thread tile: rows rg*8..+7, cols cg*4..+3 (2 col-pairs)
    unsigned long long acc2[8][2];
    #pragma unroll
    for (int r = 0; r < 8; r++) { acc2[r][0] = 0ull; acc2[r][1] = 0ull; }

    float4 pv[2];
    #pragma unroll
    for (int i = 0; i < 2; i++) pv[i] = *(const float4*)&g_wproj_t[t * 4 + i * 1024];
    #pragma unroll
    for (int i = 0; i < 2; i++) ((float4*)&sm[BS])[t + i * 256] = pv[i];
    #pragma unroll
    for (int i = 0; i < 2; i++)
        pv[i] = *(const float4*)&g_wproj_t[2048 + t * 4 + i * 1024];
    __syncthreads();

    #pragma unroll 1
    for (int s = 0; s < 32; s++) {
        const float* xb = &sm[XN2 + s * (8 * XN_STRIDE) + rg * 8];
        const float* bb = &sm[BS + (s & 1) * 2048 + cg * 4];
        #pragma unroll
        for (int kk = 0; kk < 8; kk++) {
            float4 a0 = *(const float4*)(xb + kk * XN_STRIDE);
            float4 a1 = *(const float4*)(xb + kk * XN_STRIDE + 4);
            unsigned long long A[8];
            A[0] = pack2(a0.x); A[1] = pack2(a0.y);
            A[2] = pack2(a0.z); A[3] = pack2(a0.w);
            A[4] = pack2(a1.x); A[5] = pack2(a1.y);
            A[6] = pack2(a1.z); A[7] = pack2(a1.w);
            ulonglong2 Bv = *(const ulonglong2*)(bb + kk * 256);
            #pragma unroll
            for (int r = 0; r < 8; r++) {
                fma2(acc2[r][0], A[r], Bv.x);
                fma2(acc2[r][1], A[r], Bv.y);
            }
        }
        if (s + 1 < 32) {
            #pragma unroll
            for (int i = 0; i < 2; i++)
                ((float4*)&sm[BS + ((s + 1) & 1) * 2048])[t + i * 256] = pv[i];
            if (s + 2 < 32) {
                #pragma unroll
                for (int i = 0; i < 2; i++)
                    pv[i] = *(const float4*)&g_wproj_t[(s + 2) * 2048 + t * 4 + i * 1024];
            }
        }
        __syncthreads();
    }

    // epilogue: residual + bias, park result in QKV region
    {
        float bp0 = __ldg(&bproj[cg * 4 + 0]);
        float bp1 = __ldg(&bproj[cg * 4 + 1]);
        float bp2 = __ldg(&bproj[cg * 4 + 2]);
        float bp3 = __ldg(&bproj[cg * 4 + 3]);
        #pragma unroll
        for (int r = 0; r < 8; r++) {
            int row = rg * 8 + r;
            const float* xs = &sm[X_S + row * X_STRIDE + cg * 4];
            float* o = &sm[QKV + row * QKV_STRIDE + cg * 4];
            float lo, hi;
            unpack2(acc2[r][0], lo, hi);
            o[0] = lo + xs[0] + bp0;
            o[1] = hi + xs[1] + bp1;
            unpack2(acc2[r][1], lo, hi);
            o[2] = lo + xs[2] + bp2;
            o[3] = hi + xs[3] + bp3;
        }
    }
    __syncthreads();

    // ---- Phase F: coalesced store ----
    #pragma unroll
    for (int i = 0; i < 32; i++) {
        int idx = i * 256 + t;
        int c = idx >> 5, r = idx & 31;
        og[(long long)c * 4096 + r] = sm[QKV + r * QKV_STRIDE + c];
    }
}

extern "C" void kernel_launch(void* const* d_in, const int* in_sizes, int n_in,
                              void* d_out, int out_size)
{
    const float* x     = (const float*)d_in[0];
    const float* wqkv  = (const float*)d_in[1];
    const float* wproj = (const float*)d_in[2];
    const float* bproj = (const float*)d_in[3];
    const float* gamma = (const float*)d_in[4];
    const float* beta  = (const float*)d_in[5];
    float* out = (float*)d_out;

    transpose_w_kernel<<<(768 * 256 + 255) / 256, 256>>>(wqkv, wproj);

    const size_t shmem = SMEM_FLOATS * sizeof(float);   // 218368 B
    cudaFuncSetAttribute(cva_kernel, cudaFuncAttributeMaxDynamicSharedMemorySize,
                         (int)shmem);
    cva_kernel<<<4096, 256, shmem>>>(x, bproj, gamma, beta, out);
}